// round 9
// baseline (speedup 1.0000x reference)
#include <cuda_runtime.h>
#include <cuda_bf16.h>
#include <cuda_fp16.h>
#include <cstdint>
#include <cfloat>
#include <climits>

// Problem dims (fixed per reference)
#define N_SAMPLES 131072
#define N_CENT    2048
#define DIM       256

#define BM 128
#define BN 128
#define BK 32
#define SSTRIDE 40            // halves per tile row (32 + 8 pad); conflict-free
#define TILE_HALVES (128 * SSTRIDE)   // 5120
#define NT (N_CENT / BN)      // 16
#define KT (DIM / BK)         // 8
#define NSTEPS (NT * KT)      // 128

#define MARGIN 3.0f
#define MAXCAND 16

// ---------------- scratch (static device globals; no runtime alloc) ----------------
__device__ __nv_bfloat16 g_xb[(size_t)N_SAMPLES * DIM];  // x in bf16 (64 MB)
__device__ __nv_bfloat16 g_cb[(size_t)N_CENT * DIM];     // centroids bf16 (1 MB)
__device__ float         g_csq[N_CENT];                   // ||c||^2 fp32
__device__ float         g_sums[(size_t)N_CENT * DIM];    // scatter sums
__device__ int           g_counts[N_CENT];

// ---------------- K0: zero sums + counts ----------------
__global__ void k_zero() {
    int i = blockIdx.x * blockDim.x + threadIdx.x;
    if (i < N_CENT * DIM) g_sums[i] = 0.0f;
    if (i < N_CENT) g_counts[i] = 0;
}

// ---------------- K1a: convert x -> bf16 ----------------
__global__ void k_convert_x(const float* __restrict__ x) {
    size_t i = (size_t)blockIdx.x * blockDim.x + threadIdx.x;
    const size_t n4 = (size_t)N_SAMPLES * DIM / 4;
    if (i >= n4) return;
    float4 v = reinterpret_cast<const float4*>(x)[i];
    __nv_bfloat162 p0 = __nv_bfloat162(__float2bfloat16(v.x), __float2bfloat16(v.y));
    __nv_bfloat162 p1 = __nv_bfloat162(__float2bfloat16(v.z), __float2bfloat16(v.w));
    *reinterpret_cast<__nv_bfloat162*>(g_xb + i * 4)     = p0;
    *reinterpret_cast<__nv_bfloat162*>(g_xb + i * 4 + 2) = p1;
}

// ---------------- K1b: centroids -> bf16 + csq ----------------
__global__ void k_convert_c(const float* __restrict__ c) {
    int warp = (blockIdx.x * blockDim.x + threadIdx.x) / 32;
    int lane = threadIdx.x & 31;
    if (warp >= N_CENT) return;
    const float* row = c + (size_t)warp * DIM + lane * 8;
    float4 a = *reinterpret_cast<const float4*>(row);
    float4 b = *reinterpret_cast<const float4*>(row + 4);
    __nv_bfloat16* dst = g_cb + (size_t)warp * DIM + lane * 8;
    dst[0] = __float2bfloat16(a.x); dst[1] = __float2bfloat16(a.y);
    dst[2] = __float2bfloat16(a.z); dst[3] = __float2bfloat16(a.w);
    dst[4] = __float2bfloat16(b.x); dst[5] = __float2bfloat16(b.y);
    dst[6] = __float2bfloat16(b.z); dst[7] = __float2bfloat16(b.w);
    float s = a.x*a.x + a.y*a.y + a.z*a.z + a.w*a.w
            + b.x*b.x + b.y*b.y + b.z*b.z + b.w*b.w;
    #pragma unroll
    for (int off = 16; off; off >>= 1) s += __shfl_xor_sync(0xffffffffu, s, off);
    if (lane == 0) g_csq[warp] = s;
}

// ---------------- helpers ----------------
__device__ __forceinline__ void cp_async16(uint32_t smem_addr, const void* gptr) {
    asm volatile("cp.async.cg.shared.global [%0], [%1], 16;\n"
                 :: "r"(smem_addr), "l"(gptr));
}
__device__ __forceinline__ unsigned fenc(float f) {
    unsigned u = __float_as_uint(f);
    return (u & 0x80000000u) ? ~u : (u | 0x80000000u);
}
__device__ __forceinline__ float fdec(unsigned u) {
    u = (u & 0x80000000u) ? (u & 0x7FFFFFFFu) : ~u;
    return __uint_as_float(u);
}

// smem layout (dynamic):
//   sA      : 8 * 5120 halves   = 81920 B   (A rows resident, all K)
//   sB      : 2 * 5120 halves   = 20480 B   (B tile double buffer)
//   s_cnt   : 128 int           = 512 B
//   s_rowmin: 128 uint          = 512 B
//   s_cand  : 128 * 16 int      = 8192 B
#define SMEM_SA   0
#define SMEM_SB   81920
#define SMEM_CNT  102400
#define SMEM_RMIN 102912
#define SMEM_CAND 103424
#define SMEM_TOTAL 111616

extern __shared__ unsigned char s_raw[];

// ---------------- K2: fused GEMM + argmin + candidate collect + rescore + scatter ----------------
__global__ __launch_bounds__(256, 2) void k_fused(const float* __restrict__ x,
                                                  const float* __restrict__ cent) {
    __nv_bfloat16* sA   = reinterpret_cast<__nv_bfloat16*>(s_raw + SMEM_SA);
    __nv_bfloat16* sB   = reinterpret_cast<__nv_bfloat16*>(s_raw + SMEM_SB);
    int*      s_cnt     = reinterpret_cast<int*>(s_raw + SMEM_CNT);
    unsigned* s_rowmin  = reinterpret_cast<unsigned*>(s_raw + SMEM_RMIN);
    int*      s_cand    = reinterpret_cast<int*>(s_raw + SMEM_CAND);

    const int tid  = threadIdx.x;
    const int warp = tid >> 5, lane = tid & 31;
    const int wm = warp & 3, wn = warp >> 2;
    const int g  = lane >> 4 ? 0 : 0;  // placeholder avoided; real below
    const int gg = lane >> 2, t4 = lane & 3;
    const int rowBase = blockIdx.x * BM;

    if (tid < 128) { s_cnt[tid] = 0; s_rowmin[tid] = 0xFFFFFFFFu; }

    // ---- preload all A tiles (group 0) ----
    #pragma unroll
    for (int it = 0; it < 16; it++) {
        int j  = tid + it * 256;       // 0..4095
        int kt = j >> 9;               // 0..7
        int i  = j & 511;
        int r  = i >> 2;
        int cc = (i & 3) * 8;
        uint32_t dst = (uint32_t)__cvta_generic_to_shared(sA + kt * TILE_HALVES + r * SSTRIDE + cc);
        cp_async16(dst, g_xb + (size_t)(rowBase + r) * DIM + kt * BK + cc);
    }
    asm volatile("cp.async.commit_group;\n" ::: "memory");

    // ---- B stage loader ----
    const int br0 = tid >> 2;
    const int bcc = (tid & 3) * 8;
    auto loadB = [&](int s) {
        int nt = s >> 3, kt = s & 7, buf = s & 1;
        uint32_t d0 = (uint32_t)__cvta_generic_to_shared(sB + buf * TILE_HALVES + br0 * SSTRIDE + bcc);
        uint32_t d1 = (uint32_t)__cvta_generic_to_shared(sB + buf * TILE_HALVES + (br0 + 64) * SSTRIDE + bcc);
        cp_async16(d0, g_cb + (size_t)(nt * BN + br0) * DIM + kt * BK + bcc);
        cp_async16(d1, g_cb + (size_t)(nt * BN + br0 + 64) * DIM + kt * BK + bcc);
        asm volatile("cp.async.commit_group;\n" ::: "memory");
    };
    loadB(0);

    float acc[2][8][4];
    #pragma unroll
    for (int a = 0; a < 2; a++)
        #pragma unroll
        for (int b = 0; b < 8; b++)
            #pragma unroll
            for (int c = 0; c < 4; c++) acc[a][b][c] = 0.0f;

    // rows owned by this thread (fixed across all tiles)
    const int R0 = wm * 32 + gg;
    // R[q] = R0 + {0, 8, 16, 24} for q = 0..3

    for (int s = 0; s < NSTEPS; s++) {
        if (s + 1 < NSTEPS) {
            loadB(s + 1);
            asm volatile("cp.async.wait_group 1;\n" ::: "memory");
        } else {
            asm volatile("cp.async.wait_group 0;\n" ::: "memory");
        }
        __syncthreads();

        const __nv_bfloat16* cA = sA + (s & 7) * TILE_HALVES;
        const __nv_bfloat16* cB = sB + (s & 1) * TILE_HALVES;
        #pragma unroll
        for (int kk = 0; kk < BK; kk += 16) {
            uint32_t af[2][4];
            #pragma unroll
            for (int mi = 0; mi < 2; mi++) {
                int r = wm * 32 + mi * 16 + gg;
                af[mi][0] = *reinterpret_cast<const uint32_t*>(cA + r * SSTRIDE + kk + t4 * 2);
                af[mi][1] = *reinterpret_cast<const uint32_t*>(cA + (r + 8) * SSTRIDE + kk + t4 * 2);
                af[mi][2] = *reinterpret_cast<const uint32_t*>(cA + r * SSTRIDE + kk + t4 * 2 + 8);
                af[mi][3] = *reinterpret_cast<const uint32_t*>(cA + (r + 8) * SSTRIDE + kk + t4 * 2 + 8);
            }
            uint32_t bfr[8][2];
            #pragma unroll
            for (int ni = 0; ni < 8; ni++) {
                int n = wn * 64 + ni * 8 + gg;
                bfr[ni][0] = *reinterpret_cast<const uint32_t*>(cB + n * SSTRIDE + kk + t4 * 2);
                bfr[ni][1] = *reinterpret_cast<const uint32_t*>(cB + n * SSTRIDE + kk + t4 * 2 + 8);
            }
            #pragma unroll
            for (int mi = 0; mi < 2; mi++)
                #pragma unroll
                for (int ni = 0; ni < 8; ni++) {
                    asm volatile(
                        "mma.sync.aligned.m16n8k16.row.col.f32.bf16.bf16.f32 "
                        "{%0,%1,%2,%3}, {%4,%5,%6,%7}, {%8,%9}, {%0,%1,%2,%3};\n"
                        : "+f"(acc[mi][ni][0]), "+f"(acc[mi][ni][1]),
                          "+f"(acc[mi][ni][2]), "+f"(acc[mi][ni][3])
                        : "r"(af[mi][0]), "r"(af[mi][1]), "r"(af[mi][2]), "r"(af[mi][3]),
                          "r"(bfr[ni][0]), "r"(bfr[ni][1]));
                }
        }
        __syncthreads();

        if ((s & 7) == 7) {
            // ---- epilogue for n-tile nt: scores, prefix row-min, candidate collect ----
            const int nt = s >> 3;
            const int colb = nt * BN + wn * 64;

            float tm[4] = {FLT_MAX, FLT_MAX, FLT_MAX, FLT_MAX};
            #pragma unroll
            for (int ni = 0; ni < 8; ni++) {
                float2 cq = __ldg(reinterpret_cast<const float2*>(g_csq + colb + ni * 8 + t4 * 2));
                #pragma unroll
                for (int mi = 0; mi < 2; mi++) {
                    float s0 = fmaf(-2.0f, acc[mi][ni][0], cq.x);
                    float s1 = fmaf(-2.0f, acc[mi][ni][1], cq.y);
                    float s2 = fmaf(-2.0f, acc[mi][ni][2], cq.x);
                    float s3 = fmaf(-2.0f, acc[mi][ni][3], cq.y);
                    acc[mi][ni][0] = s0; acc[mi][ni][1] = s1;
                    acc[mi][ni][2] = s2; acc[mi][ni][3] = s3;
                    tm[mi * 2]     = fminf(tm[mi * 2],     fminf(s0, s1));
                    tm[mi * 2 + 1] = fminf(tm[mi * 2 + 1], fminf(s2, s3));
                }
            }
            #pragma unroll
            for (int q = 0; q < 4; q++)
                atomicMin(&s_rowmin[R0 + q * 8], fenc(tm[q]));
            __syncthreads();

            float th[4];
            #pragma unroll
            for (int q = 0; q < 4; q++)
                th[q] = fdec(s_rowmin[R0 + q * 8]) + MARGIN;

            #pragma unroll
            for (int ni = 0; ni < 8; ni++)
                #pragma unroll
                for (int mi = 0; mi < 2; mi++)
                    #pragma unroll
                    for (int e = 0; e < 4; e++) {
                        float sv = acc[mi][ni][e];
                        int q = mi * 2 + (e >> 1);
                        if (sv <= th[q]) {
                            int r = R0 + q * 8;
                            int k = colb + ni * 8 + t4 * 2 + (e & 1);
                            int p = atomicAdd(&s_cnt[r], 1);
                            if (p < MAXCAND) s_cand[r * MAXCAND + p] = k;
                        }
                    }
            // reset accumulators for next n-tile
            #pragma unroll
            for (int a = 0; a < 2; a++)
                #pragma unroll
                for (int b = 0; b < 8; b++)
                    #pragma unroll
                    for (int c = 0; c < 4; c++) acc[a][b][c] = 0.0f;
        }
    }
    __syncthreads();

    // ---- warp-cooperative exact (double) rescore + fused scatter ----
    // warp w handles rows [w*16, w*16+16)
    for (int rr = 0; rr < 16; rr++) {
        const int r = warp * 16 + rr;
        const int grow = rowBase + r;
        const float* xr = x + (size_t)grow * DIM + lane * 8;
        float4 xa = *reinterpret_cast<const float4*>(xr);
        float4 xb = *reinterpret_cast<const float4*>(xr + 4);

        int cnt = s_cnt[r];
        if (cnt > MAXCAND) cnt = MAXCAND;

        double bestS = DBL_MAX;
        int bestK = INT_MAX;
        for (int ci = 0; ci < cnt; ci++) {
            int k = s_cand[r * MAXCAND + ci];
            const float* crow = cent + (size_t)k * DIM + lane * 8;
            float4 c0 = *reinterpret_cast<const float4*>(crow);
            float4 c1 = *reinterpret_cast<const float4*>(crow + 4);
            double dot = 0.0, cs = 0.0, cv;
            cv = (double)c0.x; dot += cv * (double)xa.x; cs += cv * cv;
            cv = (double)c0.y; dot += cv * (double)xa.y; cs += cv * cv;
            cv = (double)c0.z; dot += cv * (double)xa.z; cs += cv * cv;
            cv = (double)c0.w; dot += cv * (double)xa.w; cs += cv * cv;
            cv = (double)c1.x; dot += cv * (double)xb.x; cs += cv * cv;
            cv = (double)c1.y; dot += cv * (double)xb.y; cs += cv * cv;
            cv = (double)c1.z; dot += cv * (double)xb.z; cs += cv * cv;
            cv = (double)c1.w; dot += cv * (double)xb.w; cs += cv * cv;
            #pragma unroll
            for (int off = 16; off; off >>= 1) {
                dot += __shfl_xor_sync(0xffffffffu, dot, off);
                cs  += __shfl_xor_sync(0xffffffffu, cs,  off);
            }
            double sc = cs - 2.0 * dot;
            if (sc < bestS || (sc == bestS && k < bestK)) { bestS = sc; bestK = k; }
        }
        const int kstar = bestK;  // identical across lanes (butterfly reduction)

        if (lane == 0) atomicAdd(&g_counts[kstar], 1);
        float* dst = g_sums + (size_t)kstar * DIM + lane * 8;
        asm volatile("red.global.add.v4.f32 [%0], {%1,%2,%3,%4};\n"
                     :: "l"(dst), "f"(xa.x), "f"(xa.y), "f"(xa.z), "f"(xa.w) : "memory");
        asm volatile("red.global.add.v4.f32 [%0], {%1,%2,%3,%4};\n"
                     :: "l"(dst + 4), "f"(xb.x), "f"(xb.y), "f"(xb.z), "f"(xb.w) : "memory");
    }
}

// ---------------- K4: finalize ----------------
__global__ void k_finalize(const float* __restrict__ cent, float* __restrict__ out) {
    int i = blockIdx.x * blockDim.x + threadIdx.x;
    if (i >= N_CENT * DIM) return;
    int k = i >> 8;
    int cnt = g_counts[k];
    out[i] = (cnt > 0) ? (g_sums[i] / (float)cnt) : cent[i];
}

// ---------------- launcher ----------------
extern "C" void kernel_launch(void* const* d_in, const int* in_sizes, int n_in,
                              void* d_out, int out_size) {
    const float* x    = (const float*)d_in[0];   // (131072, 256)
    const float* cent = (const float*)d_in[1];   // (2048, 256)
    float* out = (float*)d_out;                  // (2048, 256)

    cudaFuncSetAttribute(k_fused, cudaFuncAttributeMaxDynamicSharedMemorySize, SMEM_TOTAL);

    k_zero<<<(N_CENT * DIM + 255) / 256, 256>>>();
    k_convert_x<<<(N_SAMPLES * DIM / 4 + 255) / 256, 256>>>(x);
    k_convert_c<<<N_CENT * 32 / 256, 256>>>(cent);

    k_fused<<<N_SAMPLES / BM, 256, SMEM_TOTAL>>>(x, cent);

    k_finalize<<<(N_CENT * DIM + 255) / 256, 256>>>(cent, out);
}

// round 10
// speedup vs baseline: 1.7012x; 1.7012x over previous
#include <cuda_runtime.h>
#include <cuda_bf16.h>
#include <cuda_fp16.h>
#include <cstdint>
#include <cfloat>
#include <climits>

// Problem dims (fixed per reference)
#define N_SAMPLES 131072
#define N_CENT    2048
#define DIM       256

#define BM 128
#define BN 128
#define BK 32
#define SSTRIDE 40            // halves; 80B rows -> 16B aligned + conflict-free
#define KTILES (DIM / BK)     // 8

#define MARGIN 3.0f
#define GCAND  32

// ---------------- scratch (static device globals; no runtime alloc) ----------------
__device__ __nv_bfloat16 g_xb[(size_t)N_SAMPLES * DIM];   // x in bf16 (64 MB)
__device__ __nv_bfloat16 g_cb[(size_t)N_CENT * DIM];      // centroids bf16 (1 MB)
__device__ float         g_csq[N_CENT];                    // ||c||^2 fp32
__device__ float         g_sums[(size_t)N_CENT * DIM];     // scatter sums
__device__ int           g_counts[N_CENT];
__device__ unsigned      g_rowmin[N_SAMPLES];              // order-encoded running min per row
__device__ int           g_cnt[N_SAMPLES];                 // candidates per row
__device__ float2        g_cand[(size_t)N_SAMPLES * GCAND];// (score, k-as-float-bits)

// ---------------- helpers ----------------
__device__ __forceinline__ void cp_async16(uint32_t smem_addr, const void* gptr) {
    asm volatile("cp.async.cg.shared.global [%0], [%1], 16;\n"
                 :: "r"(smem_addr), "l"(gptr));
}
__device__ __forceinline__ unsigned fenc(float f) {
    unsigned u = __float_as_uint(f);
    return (u & 0x80000000u) ? ~u : (u | 0x80000000u);
}
__device__ __forceinline__ float fdec(unsigned u) {
    u = (u & 0x80000000u) ? (u & 0x7FFFFFFFu) : ~u;
    return __uint_as_float(u);
}

// ---------------- K0: zero/init scratch ----------------
__global__ void k_zero() {
    int i = blockIdx.x * blockDim.x + threadIdx.x;
    if (i < N_CENT * DIM) g_sums[i] = 0.0f;
    if (i < N_CENT) g_counts[i] = 0;
    if (i < N_SAMPLES) { g_cnt[i] = 0; g_rowmin[i] = 0xFFFFFFFFu; }
}

// ---------------- K1a: convert x -> bf16 ----------------
__global__ void k_convert_x(const float* __restrict__ x) {
    size_t i = (size_t)blockIdx.x * blockDim.x + threadIdx.x;
    const size_t n4 = (size_t)N_SAMPLES * DIM / 4;
    if (i >= n4) return;
    float4 v = reinterpret_cast<const float4*>(x)[i];
    __nv_bfloat162 p0 = __nv_bfloat162(__float2bfloat16(v.x), __float2bfloat16(v.y));
    __nv_bfloat162 p1 = __nv_bfloat162(__float2bfloat16(v.z), __float2bfloat16(v.w));
    *reinterpret_cast<__nv_bfloat162*>(g_xb + i * 4)     = p0;
    *reinterpret_cast<__nv_bfloat162*>(g_xb + i * 4 + 2) = p1;
}

// ---------------- K1b: centroids -> bf16 + csq ----------------
__global__ void k_convert_c(const float* __restrict__ c) {
    int warp = (blockIdx.x * blockDim.x + threadIdx.x) / 32;
    int lane = threadIdx.x & 31;
    if (warp >= N_CENT) return;
    const float* row = c + (size_t)warp * DIM + lane * 8;
    float4 a = *reinterpret_cast<const float4*>(row);
    float4 b = *reinterpret_cast<const float4*>(row + 4);
    __nv_bfloat16* dst = g_cb + (size_t)warp * DIM + lane * 8;
    dst[0] = __float2bfloat16(a.x); dst[1] = __float2bfloat16(a.y);
    dst[2] = __float2bfloat16(a.z); dst[3] = __float2bfloat16(a.w);
    dst[4] = __float2bfloat16(b.x); dst[5] = __float2bfloat16(b.y);
    dst[6] = __float2bfloat16(b.z); dst[7] = __float2bfloat16(b.w);
    float s = a.x*a.x + a.y*a.y + a.z*a.z + a.w*a.w
            + b.x*b.x + b.y*b.y + b.z*b.z + b.w*b.w;
    #pragma unroll
    for (int off = 16; off; off >>= 1) s += __shfl_xor_sync(0xffffffffu, s, off);
    if (lane == 0) g_csq[warp] = s;
}

// ---------------- K2: proven MMA GEMM + min/candidate epilogue (no dots buffer) ----------------
__global__ __launch_bounds__(256, 2) void k_gemm() {
    __shared__ __nv_bfloat16 sA[2][BM * SSTRIDE];
    __shared__ __nv_bfloat16 sB[2][BN * SSTRIDE];
    __shared__ unsigned s_min[BM];

    const int tid  = threadIdx.x;
    const int warp = tid >> 5, lane = tid & 31;
    const int wm = warp & 3, wn = warp >> 2;
    const int g  = lane >> 2, t4 = lane & 3;
    const int rowBase = blockIdx.x * BM;
    const int colBase = blockIdx.y * BN;

    if (tid < BM) s_min[tid] = 0xFFFFFFFFu;

    const int r0 = tid >> 2;
    const int r1 = r0 + 64;
    const int cc = (tid & 3) * 8;

    float acc[2][8][4];
    #pragma unroll
    for (int a = 0; a < 2; a++)
        #pragma unroll
        for (int b = 0; b < 8; b++)
            #pragma unroll
            for (int c = 0; c < 4; c++) acc[a][b][c] = 0.0f;

    auto load_stage = [&](int buf, int k0) {
        uint32_t a0 = (uint32_t)__cvta_generic_to_shared(sA[buf] + r0 * SSTRIDE + cc);
        uint32_t a1 = (uint32_t)__cvta_generic_to_shared(sA[buf] + r1 * SSTRIDE + cc);
        uint32_t b0 = (uint32_t)__cvta_generic_to_shared(sB[buf] + r0 * SSTRIDE + cc);
        uint32_t b1 = (uint32_t)__cvta_generic_to_shared(sB[buf] + r1 * SSTRIDE + cc);
        cp_async16(a0, g_xb + (size_t)(rowBase + r0) * DIM + k0 + cc);
        cp_async16(a1, g_xb + (size_t)(rowBase + r1) * DIM + k0 + cc);
        cp_async16(b0, g_cb + (size_t)(colBase + r0) * DIM + k0 + cc);
        cp_async16(b1, g_cb + (size_t)(colBase + r1) * DIM + k0 + cc);
    };

    load_stage(0, 0);
    asm volatile("cp.async.commit_group;\n" ::: "memory");

    for (int kt = 0; kt < KTILES; kt++) {
        const int buf = kt & 1;
        if (kt + 1 < KTILES) {
            load_stage((kt + 1) & 1, (kt + 1) * BK);
            asm volatile("cp.async.commit_group;\n" ::: "memory");
            asm volatile("cp.async.wait_group 1;\n" ::: "memory");
        } else {
            asm volatile("cp.async.wait_group 0;\n" ::: "memory");
        }
        __syncthreads();

        const __nv_bfloat16* cA = sA[buf];
        const __nv_bfloat16* cB = sB[buf];
        #pragma unroll
        for (int kk = 0; kk < BK; kk += 16) {
            uint32_t af[2][4];
            #pragma unroll
            for (int mi = 0; mi < 2; mi++) {
                int r = wm * 32 + mi * 16 + g;
                af[mi][0] = *reinterpret_cast<const uint32_t*>(cA + r * SSTRIDE + kk + t4 * 2);
                af[mi][1] = *reinterpret_cast<const uint32_t*>(cA + (r + 8) * SSTRIDE + kk + t4 * 2);
                af[mi][2] = *reinterpret_cast<const uint32_t*>(cA + r * SSTRIDE + kk + t4 * 2 + 8);
                af[mi][3] = *reinterpret_cast<const uint32_t*>(cA + (r + 8) * SSTRIDE + kk + t4 * 2 + 8);
            }
            uint32_t bfr[8][2];
            #pragma unroll
            for (int ni = 0; ni < 8; ni++) {
                int n = wn * 64 + ni * 8 + g;
                bfr[ni][0] = *reinterpret_cast<const uint32_t*>(cB + n * SSTRIDE + kk + t4 * 2);
                bfr[ni][1] = *reinterpret_cast<const uint32_t*>(cB + n * SSTRIDE + kk + t4 * 2 + 8);
            }
            #pragma unroll
            for (int mi = 0; mi < 2; mi++)
                #pragma unroll
                for (int ni = 0; ni < 8; ni++) {
                    asm volatile(
                        "mma.sync.aligned.m16n8k16.row.col.f32.bf16.bf16.f32 "
                        "{%0,%1,%2,%3}, {%4,%5,%6,%7}, {%8,%9}, {%0,%1,%2,%3};\n"
                        : "+f"(acc[mi][ni][0]), "+f"(acc[mi][ni][1]),
                          "+f"(acc[mi][ni][2]), "+f"(acc[mi][ni][3])
                        : "r"(af[mi][0]), "r"(af[mi][1]), "r"(af[mi][2]), "r"(af[mi][3]),
                          "r"(bfr[ni][0]), "r"(bfr[ni][1]));
                }
        }
        __syncthreads();
    }

    // ---- epilogue (acc dead into it; main loop untouched) ----
    // scores in place: s = csq[col] - 2*dot ; per-thread row minima
    float tm[2][2] = {{FLT_MAX, FLT_MAX}, {FLT_MAX, FLT_MAX}};
    #pragma unroll
    for (int ni = 0; ni < 8; ni++) {
        float2 cq = __ldg(reinterpret_cast<const float2*>(g_csq + colBase + wn * 64 + ni * 8 + t4 * 2));
        #pragma unroll
        for (int mi = 0; mi < 2; mi++) {
            acc[mi][ni][0] = fmaf(-2.0f, acc[mi][ni][0], cq.x);
            acc[mi][ni][1] = fmaf(-2.0f, acc[mi][ni][1], cq.y);
            acc[mi][ni][2] = fmaf(-2.0f, acc[mi][ni][2], cq.x);
            acc[mi][ni][3] = fmaf(-2.0f, acc[mi][ni][3], cq.y);
            tm[mi][0] = fminf(tm[mi][0], fminf(acc[mi][ni][0], acc[mi][ni][1]));
            tm[mi][1] = fminf(tm[mi][1], fminf(acc[mi][ni][2], acc[mi][ni][3]));
        }
    }
    #pragma unroll
    for (int mi = 0; mi < 2; mi++)
        #pragma unroll
        for (int h = 0; h < 2; h++)
            atomicMin(&s_min[wm * 32 + mi * 16 + g + h * 8], fenc(tm[mi][h]));
    __syncthreads();

    // merge block min into global running row-min; pull tighter global bound back in
    if (t4 == 0) {
        #pragma unroll
        for (int mi = 0; mi < 2; mi++)
            #pragma unroll
            for (int h = 0; h < 2; h++) {
                int lr = wm * 32 + mi * 16 + g + h * 8;
                unsigned mine = s_min[lr];
                unsigned oldg = atomicMin(&g_rowmin[rowBase + lr], mine);
                if (oldg < mine) atomicMin(&s_min[lr], oldg);
            }
    }
    __syncthreads();

    // append candidates within MARGIN of best-known min (superset of final margin set)
    #pragma unroll
    for (int mi = 0; mi < 2; mi++) {
        #pragma unroll
        for (int h = 0; h < 2; h++) {
            const int lr = wm * 32 + mi * 16 + g + h * 8;
            const float th = fdec(s_min[lr]) + MARGIN;
            const int grow = rowBase + lr;
            #pragma unroll
            for (int ni = 0; ni < 8; ni++) {
                #pragma unroll
                for (int e = 0; e < 2; e++) {
                    float sv = acc[mi][ni][h * 2 + e];
                    if (sv <= th) {
                        int k = colBase + wn * 64 + ni * 8 + t4 * 2 + e;
                        int p = atomicAdd(&g_cnt[grow], 1);
                        if (p < GCAND)
                            g_cand[(size_t)grow * GCAND + p] = make_float2(sv, __int_as_float(k));
                    }
                }
            }
        }
    }
}

// ---------------- K3: filter + warp-cooperative fp64 rescore + fused scatter ----------------
__global__ __launch_bounds__(256) void k_assign(const float* __restrict__ x,
                                                const float* __restrict__ cent) {
    const int tid = threadIdx.x;
    const int warp = tid >> 5, lane = tid & 31;
    const int row = blockIdx.x * 8 + warp;

    int cnt = g_cnt[row];
    if (cnt > GCAND) cnt = GCAND;
    const float th = fdec(g_rowmin[row]) + MARGIN;

    const float* xr = x + (size_t)row * DIM + lane * 8;
    float4 xa = *reinterpret_cast<const float4*>(xr);
    float4 xb = *reinterpret_cast<const float4*>(xr + 4);

    double bestS = DBL_MAX;
    int bestK = INT_MAX;
    const float2* clist = g_cand + (size_t)row * GCAND;
    for (int ci = 0; ci < cnt; ci++) {
        float2 cand = __ldg(clist + ci);   // broadcast load (same addr all lanes)
        if (cand.x > th) continue;
        int k = __float_as_int(cand.y);
        const float* crow = cent + (size_t)k * DIM + lane * 8;
        float4 c0 = *reinterpret_cast<const float4*>(crow);
        float4 c1 = *reinterpret_cast<const float4*>(crow + 4);
        double dot = 0.0, cs = 0.0, cv;
        cv = (double)c0.x; dot += cv * (double)xa.x; cs += cv * cv;
        cv = (double)c0.y; dot += cv * (double)xa.y; cs += cv * cv;
        cv = (double)c0.z; dot += cv * (double)xa.z; cs += cv * cv;
        cv = (double)c0.w; dot += cv * (double)xa.w; cs += cv * cv;
        cv = (double)c1.x; dot += cv * (double)xb.x; cs += cv * cv;
        cv = (double)c1.y; dot += cv * (double)xb.y; cs += cv * cv;
        cv = (double)c1.z; dot += cv * (double)xb.z; cs += cv * cv;
        cv = (double)c1.w; dot += cv * (double)xb.w; cs += cv * cv;
        #pragma unroll
        for (int off = 16; off; off >>= 1) {
            dot += __shfl_xor_sync(0xffffffffu, dot, off);
            cs  += __shfl_xor_sync(0xffffffffu, cs,  off);
        }
        double sc = cs - 2.0 * dot;
        if (sc < bestS || (sc == bestS && k < bestK)) { bestS = sc; bestK = k; }
    }
    const int kstar = bestK;  // identical across lanes (butterfly reduction)

    if (lane == 0) atomicAdd(&g_counts[kstar], 1);
    float* dst = g_sums + (size_t)kstar * DIM + lane * 8;
    asm volatile("red.global.add.v4.f32 [%0], {%1,%2,%3,%4};\n"
                 :: "l"(dst), "f"(xa.x), "f"(xa.y), "f"(xa.z), "f"(xa.w) : "memory");
    asm volatile("red.global.add.v4.f32 [%0], {%1,%2,%3,%4};\n"
                 :: "l"(dst + 4), "f"(xb.x), "f"(xb.y), "f"(xb.z), "f"(xb.w) : "memory");
}

// ---------------- K4: finalize ----------------
__global__ void k_finalize(const float* __restrict__ cent, float* __restrict__ out) {
    int i = blockIdx.x * blockDim.x + threadIdx.x;
    if (i >= N_CENT * DIM) return;
    int k = i >> 8;
    int cnt = g_counts[k];
    out[i] = (cnt > 0) ? (g_sums[i] / (float)cnt) : cent[i];
}

// ---------------- launcher ----------------
extern "C" void kernel_launch(void* const* d_in, const int* in_sizes, int n_in,
                              void* d_out, int out_size) {
    const float* x    = (const float*)d_in[0];   // (131072, 256)
    const float* cent = (const float*)d_in[1];   // (2048, 256)
    float* out = (float*)d_out;                  // (2048, 256)

    k_zero<<<(N_CENT * DIM + 255) / 256, 256>>>();
    k_convert_x<<<(N_SAMPLES * DIM / 4 + 255) / 256, 256>>>(x);
    k_convert_c<<<N_CENT * 32 / 256, 256>>>(cent);

    dim3 gg(N_SAMPLES / BM, N_CENT / BN);
    k_gemm<<<gg, 256>>>();

    k_assign<<<N_SAMPLES / 8, 256>>>(x, cent);

    k_finalize<<<(N_CENT * DIM + 255) / 256, 256>>>(cent, out);
}

// round 11
// speedup vs baseline: 1.7819x; 1.0474x over previous
#include <cuda_runtime.h>
#include <cuda_bf16.h>
#include <cuda_fp16.h>
#include <cstdint>
#include <cfloat>
#include <climits>

// Problem dims (fixed per reference)
#define N_SAMPLES 131072
#define N_CENT    2048
#define DIM       256

#define BM 128
#define BN 128
#define BK 32
#define SSTRIDE 40            // halves; 80B rows -> 16B aligned + LDSM conflict-free
#define KTILES (DIM / BK)     // 8

#define MARGIN 3.0f
#define GCAND  32

// ---------------- scratch (static device globals; no runtime alloc) ----------------
__device__ __nv_bfloat16 g_xb[(size_t)N_SAMPLES * DIM];   // x in bf16 (64 MB)
__device__ __nv_bfloat16 g_cb[(size_t)N_CENT * DIM];      // centroids bf16 (1 MB)
__device__ float         g_csq[N_CENT];                    // ||c||^2 fp32
__device__ float         g_sums[(size_t)N_CENT * DIM];     // scatter sums
__device__ int           g_counts[N_CENT];
__device__ unsigned      g_rowmin[N_SAMPLES];              // order-encoded running min per row
__device__ int           g_cnt[N_SAMPLES];                 // candidates per row
__device__ float2        g_cand[(size_t)N_SAMPLES * GCAND];// (score, k-as-float-bits)

// ---------------- helpers ----------------
__device__ __forceinline__ void cp_async16(uint32_t smem_addr, const void* gptr) {
    asm volatile("cp.async.cg.shared.global [%0], [%1], 16;\n"
                 :: "r"(smem_addr), "l"(gptr));
}
__device__ __forceinline__ void ldsm4(uint32_t& r0, uint32_t& r1, uint32_t& r2, uint32_t& r3,
                                      uint32_t addr) {
    asm volatile("ldmatrix.sync.aligned.m8n8.x4.shared.b16 {%0,%1,%2,%3}, [%4];"
                 : "=r"(r0), "=r"(r1), "=r"(r2), "=r"(r3) : "r"(addr));
}
__device__ __forceinline__ unsigned fenc(float f) {
    unsigned u = __float_as_uint(f);
    return (u & 0x80000000u) ? ~u : (u | 0x80000000u);
}
__device__ __forceinline__ float fdec(unsigned u) {
    u = (u & 0x80000000u) ? (u & 0x7FFFFFFFu) : ~u;
    return __uint_as_float(u);
}

// ---------------- K1: fused prep: zero scratch + convert x & centroids ----------------
__global__ void k_prep(const float* __restrict__ x, const float* __restrict__ c) {
    const size_t i = (size_t)blockIdx.x * blockDim.x + threadIdx.x;

    // convert one float4 of x -> 4 bf16
    const size_t n4 = (size_t)N_SAMPLES * DIM / 4;
    if (i < n4) {
        float4 v = reinterpret_cast<const float4*>(x)[i];
        __nv_bfloat162 p0 = __nv_bfloat162(__float2bfloat16(v.x), __float2bfloat16(v.y));
        __nv_bfloat162 p1 = __nv_bfloat162(__float2bfloat16(v.z), __float2bfloat16(v.w));
        *reinterpret_cast<__nv_bfloat162*>(g_xb + i * 4)     = p0;
        *reinterpret_cast<__nv_bfloat162*>(g_xb + i * 4 + 2) = p1;
    }
    if (i < (size_t)N_CENT * DIM) g_sums[i] = 0.0f;
    if (i < N_SAMPLES) { g_cnt[i] = 0; g_rowmin[i] = 0xFFFFFFFFu; }
    if (i < N_CENT) g_counts[i] = 0;

    // warp per centroid: bf16 convert + csq (warps 0..2047)
    const int w = (int)(i >> 5);
    const int lane = threadIdx.x & 31;
    if (w < N_CENT) {
        const float* row = c + (size_t)w * DIM + lane * 8;
        float4 a = *reinterpret_cast<const float4*>(row);
        float4 b = *reinterpret_cast<const float4*>(row + 4);
        __nv_bfloat16* dst = g_cb + (size_t)w * DIM + lane * 8;
        dst[0] = __float2bfloat16(a.x); dst[1] = __float2bfloat16(a.y);
        dst[2] = __float2bfloat16(a.z); dst[3] = __float2bfloat16(a.w);
        dst[4] = __float2bfloat16(b.x); dst[5] = __float2bfloat16(b.y);
        dst[6] = __float2bfloat16(b.z); dst[7] = __float2bfloat16(b.w);
        float s = a.x*a.x + a.y*a.y + a.z*a.z + a.w*a.w
                + b.x*b.x + b.y*b.y + b.z*b.z + b.w*b.w;
        #pragma unroll
        for (int off = 16; off; off >>= 1) s += __shfl_xor_sync(0xffffffffu, s, off);
        if (lane == 0) g_csq[w] = s;
    }
}

// ---------------- K2: MMA GEMM (ldmatrix fragments) + min/candidate epilogue ----------------
__global__ __launch_bounds__(256, 2) void k_gemm() {
    __shared__ __nv_bfloat16 sA[2][BM * SSTRIDE];
    __shared__ __nv_bfloat16 sB[2][BN * SSTRIDE];
    __shared__ unsigned s_min[BM];

    const int tid  = threadIdx.x;
    const int warp = tid >> 5, lane = tid & 31;
    const int wm = warp & 3, wn = warp >> 2;
    const int g  = lane >> 2, t4 = lane & 3;
    const int rowBase = blockIdx.x * BM;
    const int colBase = blockIdx.y * BN;

    if (tid < BM) s_min[tid] = 0xFFFFFFFFu;

    // cooperative-load coords
    const int r0 = tid >> 2;
    const int r1 = r0 + 64;
    const int cc = (tid & 3) * 8;

    // ldmatrix per-lane row offsets (bytes)
    const int lrow = lane & 7, sel = lane >> 3;
    const uint32_t aRowOff = ((wm * 32 + (sel & 1) * 8 + lrow) * SSTRIDE + (sel >> 1) * 8) * 2;
    const uint32_t bRowOff = ((wn * 64 + (sel >> 1) * 8 + lrow) * SSTRIDE + (sel & 1) * 8) * 2;
    const uint32_t sAb[2] = { (uint32_t)__cvta_generic_to_shared(sA[0]),
                              (uint32_t)__cvta_generic_to_shared(sA[1]) };
    const uint32_t sBb[2] = { (uint32_t)__cvta_generic_to_shared(sB[0]),
                              (uint32_t)__cvta_generic_to_shared(sB[1]) };

    float acc[2][8][4];
    #pragma unroll
    for (int a = 0; a < 2; a++)
        #pragma unroll
        for (int b = 0; b < 8; b++)
            #pragma unroll
            for (int c = 0; c < 4; c++) acc[a][b][c] = 0.0f;

    auto load_stage = [&](int buf, int k0) {
        uint32_t a0 = (uint32_t)__cvta_generic_to_shared(sA[buf] + r0 * SSTRIDE + cc);
        uint32_t a1 = (uint32_t)__cvta_generic_to_shared(sA[buf] + r1 * SSTRIDE + cc);
        uint32_t b0 = (uint32_t)__cvta_generic_to_shared(sB[buf] + r0 * SSTRIDE + cc);
        uint32_t b1 = (uint32_t)__cvta_generic_to_shared(sB[buf] + r1 * SSTRIDE + cc);
        cp_async16(a0, g_xb + (size_t)(rowBase + r0) * DIM + k0 + cc);
        cp_async16(a1, g_xb + (size_t)(rowBase + r1) * DIM + k0 + cc);
        cp_async16(b0, g_cb + (size_t)(colBase + r0) * DIM + k0 + cc);
        cp_async16(b1, g_cb + (size_t)(colBase + r1) * DIM + k0 + cc);
    };

    load_stage(0, 0);
    asm volatile("cp.async.commit_group;\n" ::: "memory");

    for (int kt = 0; kt < KTILES; kt++) {
        const int buf = kt & 1;
        if (kt + 1 < KTILES) {
            load_stage((kt + 1) & 1, (kt + 1) * BK);
            asm volatile("cp.async.commit_group;\n" ::: "memory");
            asm volatile("cp.async.wait_group 1;\n" ::: "memory");
        } else {
            asm volatile("cp.async.wait_group 0;\n" ::: "memory");
        }
        __syncthreads();

        const uint32_t aB = sAb[buf] + aRowOff;
        const uint32_t bB = sBb[buf] + bRowOff;
        #pragma unroll
        for (int kk = 0; kk < BK; kk += 16) {
            uint32_t af[2][4];
            #pragma unroll
            for (int mi = 0; mi < 2; mi++)
                ldsm4(af[mi][0], af[mi][1], af[mi][2], af[mi][3],
                      aB + (mi * 16 * SSTRIDE + kk) * 2);
            uint32_t bfr[8][2];
            #pragma unroll
            for (int p = 0; p < 4; p++)
                ldsm4(bfr[2 * p][0], bfr[2 * p][1], bfr[2 * p + 1][0], bfr[2 * p + 1][1],
                      bB + (p * 16 * SSTRIDE + kk) * 2);
            #pragma unroll
            for (int mi = 0; mi < 2; mi++)
                #pragma unroll
                for (int ni = 0; ni < 8; ni++) {
                    asm volatile(
                        "mma.sync.aligned.m16n8k16.row.col.f32.bf16.bf16.f32 "
                        "{%0,%1,%2,%3}, {%4,%5,%6,%7}, {%8,%9}, {%0,%1,%2,%3};\n"
                        : "+f"(acc[mi][ni][0]), "+f"(acc[mi][ni][1]),
                          "+f"(acc[mi][ni][2]), "+f"(acc[mi][ni][3])
                        : "r"(af[mi][0]), "r"(af[mi][1]), "r"(af[mi][2]), "r"(af[mi][3]),
                          "r"(bfr[ni][0]), "r"(bfr[ni][1]));
                }
        }
        __syncthreads();
    }

    // ---- epilogue: scores in place, per-row minima, candidate append ----
    float tm[2][2] = {{FLT_MAX, FLT_MAX}, {FLT_MAX, FLT_MAX}};
    #pragma unroll
    for (int ni = 0; ni < 8; ni++) {
        float2 cq = __ldg(reinterpret_cast<const float2*>(g_csq + colBase + wn * 64 + ni * 8 + t4 * 2));
        #pragma unroll
        for (int mi = 0; mi < 2; mi++) {
            acc[mi][ni][0] = fmaf(-2.0f, acc[mi][ni][0], cq.x);
            acc[mi][ni][1] = fmaf(-2.0f, acc[mi][ni][1], cq.y);
            acc[mi][ni][2] = fmaf(-2.0f, acc[mi][ni][2], cq.x);
            acc[mi][ni][3] = fmaf(-2.0f, acc[mi][ni][3], cq.y);
            tm[mi][0] = fminf(tm[mi][0], fminf(acc[mi][ni][0], acc[mi][ni][1]));
            tm[mi][1] = fminf(tm[mi][1], fminf(acc[mi][ni][2], acc[mi][ni][3]));
        }
    }
    #pragma unroll
    for (int mi = 0; mi < 2; mi++)
        #pragma unroll
        for (int h = 0; h < 2; h++)
            atomicMin(&s_min[wm * 32 + mi * 16 + g + h * 8], fenc(tm[mi][h]));
    __syncthreads();

    // merge block min into global running row-min; pull tighter bound back in
    if (t4 == 0) {
        #pragma unroll
        for (int mi = 0; mi < 2; mi++)
            #pragma unroll
            for (int h = 0; h < 2; h++) {
                int lr = wm * 32 + mi * 16 + g + h * 8;
                unsigned mine = s_min[lr];
                unsigned oldg = atomicMin(&g_rowmin[rowBase + lr], mine);
                if (oldg < mine) atomicMin(&s_min[lr], oldg);
            }
    }
    __syncthreads();

    // append candidates within MARGIN of best-known min (superset of final margin set)
    #pragma unroll
    for (int mi = 0; mi < 2; mi++) {
        #pragma unroll
        for (int h = 0; h < 2; h++) {
            const int lr = wm * 32 + mi * 16 + g + h * 8;
            const float th = fdec(s_min[lr]) + MARGIN;
            const int grow = rowBase + lr;
            #pragma unroll
            for (int ni = 0; ni < 8; ni++) {
                #pragma unroll
                for (int e = 0; e < 2; e++) {
                    float sv = acc[mi][ni][h * 2 + e];
                    if (sv <= th) {
                        int k = colBase + wn * 64 + ni * 8 + t4 * 2 + e;
                        int p = atomicAdd(&g_cnt[grow], 1);
                        if (p < GCAND)
                            g_cand[(size_t)grow * GCAND + p] = make_float2(sv, __int_as_float(k));
                    }
                }
            }
        }
    }
}

// ---------------- K3: lane-parallel filter + warp fp64 rescore + fused scatter ----------------
__global__ __launch_bounds__(256) void k_assign(const float* __restrict__ x,
                                                const float* __restrict__ cent) {
    const int tid = threadIdx.x;
    const int warp = tid >> 5, lane = tid & 31;
    const int row = blockIdx.x * 8 + warp;

    int cnt = g_cnt[row];
    if (cnt > GCAND) cnt = GCAND;
    const float th = fdec(g_rowmin[row]) + MARGIN;

    // lane-parallel candidate load (one coalesced 8B load per lane)
    float2 cand = make_float2(FLT_MAX, 0.0f);
    if (lane < cnt) cand = g_cand[(size_t)row * GCAND + lane];
    unsigned mask = __ballot_sync(0xffffffffu, lane < cnt && cand.x <= th);

    const float* xr = x + (size_t)row * DIM + lane * 8;
    float4 xa = *reinterpret_cast<const float4*>(xr);
    float4 xb = *reinterpret_cast<const float4*>(xr + 4);

    double bestS = DBL_MAX;
    int bestK = INT_MAX;
    while (mask) {
        const int src = __ffs(mask) - 1;
        mask &= mask - 1;
        const int k = __shfl_sync(0xffffffffu, __float_as_int(cand.y), src);
        const float* crow = cent + (size_t)k * DIM + lane * 8;
        float4 c0 = *reinterpret_cast<const float4*>(crow);
        float4 c1 = *reinterpret_cast<const float4*>(crow + 4);
        double dot = 0.0, cs = 0.0, cv;
        cv = (double)c0.x; dot += cv * (double)xa.x; cs += cv * cv;
        cv = (double)c0.y; dot += cv * (double)xa.y; cs += cv * cv;
        cv = (double)c0.z; dot += cv * (double)xa.z; cs += cv * cv;
        cv = (double)c0.w; dot += cv * (double)xa.w; cs += cv * cv;
        cv = (double)c1.x; dot += cv * (double)xb.x; cs += cv * cv;
        cv = (double)c1.y; dot += cv * (double)xb.y; cs += cv * cv;
        cv = (double)c1.z; dot += cv * (double)xb.z; cs += cv * cv;
        cv = (double)c1.w; dot += cv * (double)xb.w; cs += cv * cv;
        #pragma unroll
        for (int off = 16; off; off >>= 1) {
            dot += __shfl_xor_sync(0xffffffffu, dot, off);
            cs  += __shfl_xor_sync(0xffffffffu, cs,  off);
        }
        double sc = cs - 2.0 * dot;
        if (sc < bestS || (sc == bestS && k < bestK)) { bestS = sc; bestK = k; }
    }
    const int kstar = bestK;  // identical across lanes (butterfly reduction)

    if (lane == 0) atomicAdd(&g_counts[kstar], 1);
    float* dst = g_sums + (size_t)kstar * DIM + lane * 8;
    asm volatile("red.global.add.v4.f32 [%0], {%1,%2,%3,%4};\n"
                 :: "l"(dst), "f"(xa.x), "f"(xa.y), "f"(xa.z), "f"(xa.w) : "memory");
    asm volatile("red.global.add.v4.f32 [%0], {%1,%2,%3,%4};\n"
                 :: "l"(dst + 4), "f"(xb.x), "f"(xb.y), "f"(xb.z), "f"(xb.w) : "memory");
}

// ---------------- K4: finalize ----------------
__global__ void k_finalize(const float* __restrict__ cent, float* __restrict__ out) {
    int i = blockIdx.x * blockDim.x + threadIdx.x;
    if (i >= N_CENT * DIM) return;
    int k = i >> 8;
    int cnt = g_counts[k];
    out[i] = (cnt > 0) ? (g_sums[i] / (float)cnt) : cent[i];
}

// ---------------- launcher ----------------
extern "C" void kernel_launch(void* const* d_in, const int* in_sizes, int n_in,
                              void* d_out, int out_size) {
    const float* x    = (const float*)d_in[0];   // (131072, 256)
    const float* cent = (const float*)d_in[1];   // (2048, 256)
    float* out = (float*)d_out;                  // (2048, 256)

    k_prep<<<(N_SAMPLES * DIM / 4 + 255) / 256, 256>>>(x, cent);

    dim3 gg(N_SAMPLES / BM, N_CENT / BN);
    k_gemm<<<gg, 256>>>();

    k_assign<<<N_SAMPLES / 8, 256>>>(x, cent);

    k_finalize<<<(N_CENT * DIM + 255) / 256, 256>>>(cent, out);
}

// round 15
// speedup vs baseline: 2.4039x; 1.3491x over previous
#include <cuda_runtime.h>
#include <cuda_bf16.h>
#include <cuda_fp16.h>
#include <cstdint>
#include <cfloat>
#include <climits>

// Problem dims (fixed per reference)
#define N_SAMPLES 131072
#define N_CENT    2048
#define DIM       256

#define BM 128
#define BN 128
#define BK 32
#define SSTRIDE 40            // halves; 80B rows -> 16B aligned + LDSM conflict-free
#define KTILES (DIM / BK)     // 8
#define NSTAGE 3

#define MARGIN 3.0f
#define GCAND  32

// ---------------- scratch (static device globals; no runtime alloc) ----------------
__device__ __nv_bfloat16 g_xb[(size_t)N_SAMPLES * DIM];   // x in bf16 (64 MB)
__device__ __nv_bfloat16 g_cb[(size_t)N_CENT * DIM];      // centroids bf16 (1 MB)
__device__ float         g_csq[N_CENT];                    // ||c||^2 fp32
__device__ float         g_sums[(size_t)N_CENT * DIM];     // scatter sums
__device__ int           g_counts[N_CENT];
__device__ unsigned      g_rowmin[N_SAMPLES];              // order-encoded running min per row
__device__ int           g_cnt[N_SAMPLES];                 // candidates per row
__device__ float2        g_cand[(size_t)N_SAMPLES * GCAND];// (score, k-as-float-bits)

// ---------------- helpers ----------------
__device__ __forceinline__ void cp_async16(uint32_t smem_addr, const void* gptr) {
    asm volatile("cp.async.cg.shared.global [%0], [%1], 16;\n"
                 :: "r"(smem_addr), "l"(gptr));
}
__device__ __forceinline__ void ldsm4(uint32_t& r0, uint32_t& r1, uint32_t& r2, uint32_t& r3,
                                      uint32_t addr) {
    asm volatile("ldmatrix.sync.aligned.m8n8.x4.shared.b16 {%0,%1,%2,%3}, [%4];"
                 : "=r"(r0), "=r"(r1), "=r"(r2), "=r"(r3) : "r"(addr));
}
__device__ __forceinline__ unsigned fenc(float f) {
    unsigned u = __float_as_uint(f);
    return (u & 0x80000000u) ? ~u : (u | 0x80000000u);
}
__device__ __forceinline__ float fdec(unsigned u) {
    u = (u & 0x80000000u) ? (u & 0x7FFFFFFFu) : ~u;
    return __uint_as_float(u);
}

// ---------------- K1: fused prep: zero scratch + convert x & centroids ----------------
__global__ void k_prep(const float* __restrict__ x, const float* __restrict__ c) {
    const size_t i = (size_t)blockIdx.x * blockDim.x + threadIdx.x;

    const size_t n4 = (size_t)N_SAMPLES * DIM / 4;
    if (i < n4) {
        float4 v = reinterpret_cast<const float4*>(x)[i];
        __nv_bfloat162 p0 = __nv_bfloat162(__float2bfloat16(v.x), __float2bfloat16(v.y));
        __nv_bfloat162 p1 = __nv_bfloat162(__float2bfloat16(v.z), __float2bfloat16(v.w));
        *reinterpret_cast<__nv_bfloat162*>(g_xb + i * 4)     = p0;
        *reinterpret_cast<__nv_bfloat162*>(g_xb + i * 4 + 2) = p1;
    }
    if (i < (size_t)N_CENT * DIM) g_sums[i] = 0.0f;
    if (i < N_SAMPLES) { g_cnt[i] = 0; g_rowmin[i] = 0xFFFFFFFFu; }
    if (i < N_CENT) g_counts[i] = 0;

    const int w = (int)(i >> 5);
    const int lane = threadIdx.x & 31;
    if (w < N_CENT) {
        const float* row = c + (size_t)w * DIM + lane * 8;
        float4 a = *reinterpret_cast<const float4*>(row);
        float4 b = *reinterpret_cast<const float4*>(row + 4);
        __nv_bfloat16* dst = g_cb + (size_t)w * DIM + lane * 8;
        dst[0] = __float2bfloat16(a.x); dst[1] = __float2bfloat16(a.y);
        dst[2] = __float2bfloat16(a.z); dst[3] = __float2bfloat16(a.w);
        dst[4] = __float2bfloat16(b.x); dst[5] = __float2bfloat16(b.y);
        dst[6] = __float2bfloat16(b.z); dst[7] = __float2bfloat16(b.w);
        float s = a.x*a.x + a.y*a.y + a.z*a.z + a.w*a.w
                + b.x*b.x + b.y*b.y + b.z*b.z + b.w*b.w;
        #pragma unroll
        for (int off = 16; off; off >>= 1) s += __shfl_xor_sync(0xffffffffu, s, off);
        if (lane == 0) g_csq[w] = s;
    }
}

// smem: 3 stages of (A tile + B tile) + row-min
// stage bytes: A 128*40*2 = 10240, B same -> 20480/stage; 3 stages = 61440; s_min 512
#define STG_BYTES 20480
#define SM_MIN    (NSTAGE * STG_BYTES)
#define SM_TOTAL  (SM_MIN + 512)

extern __shared__ unsigned char s_raw[];

// ---------------- K2: MMA GEMM, 3-stage pipeline, min/candidate epilogue ----------------
__global__ __launch_bounds__(256, 2) void k_gemm() {
    const int tid  = threadIdx.x;
    const int warp = tid >> 5, lane = tid & 31;
    const int wm = warp & 3, wn = warp >> 2;
    const int g  = lane >> 2, t4 = lane & 3;
    const int rowBase = blockIdx.x * BM;
    const int colBase = blockIdx.y * BN;

    unsigned* s_min = reinterpret_cast<unsigned*>(s_raw + SM_MIN);
    if (tid < BM) s_min[tid] = 0xFFFFFFFFu;

    const uint32_t smb = (uint32_t)__cvta_generic_to_shared(s_raw);

    // cooperative-load coords
    const int r0 = tid >> 2;
    const int r1 = r0 + 64;
    const int cc = (tid & 3) * 8;

    // ldmatrix per-lane offsets (bytes, within a stage)
    const int lrow = lane & 7, sel = lane >> 3;
    const uint32_t aRowOff = ((wm * 32 + (sel & 1) * 8 + lrow) * SSTRIDE + (sel >> 1) * 8) * 2;
    const uint32_t bRowOff = 10240 + ((wn * 64 + (sel >> 1) * 8 + lrow) * SSTRIDE + (sel & 1) * 8) * 2;

    float acc[2][8][4];
    #pragma unroll
    for (int a = 0; a < 2; a++)
        #pragma unroll
        for (int b = 0; b < 8; b++)
            #pragma unroll
            for (int c = 0; c < 4; c++) acc[a][b][c] = 0.0f;

    auto load_stage = [&](int st, int k0) {
        uint32_t base = smb + st * STG_BYTES;
        cp_async16(base + (r0 * SSTRIDE + cc) * 2,
                   g_xb + (size_t)(rowBase + r0) * DIM + k0 + cc);
        cp_async16(base + (r1 * SSTRIDE + cc) * 2,
                   g_xb + (size_t)(rowBase + r1) * DIM + k0 + cc);
        cp_async16(base + 10240 + (r0 * SSTRIDE + cc) * 2,
                   g_cb + (size_t)(colBase + r0) * DIM + k0 + cc);
        cp_async16(base + 10240 + (r1 * SSTRIDE + cc) * 2,
                   g_cb + (size_t)(colBase + r1) * DIM + k0 + cc);
        asm volatile("cp.async.commit_group;\n" ::: "memory");
    };

    load_stage(0, 0);
    load_stage(1, BK);

    for (int kt = 0; kt < KTILES; kt++) {
        if (kt == KTILES - 1)
            asm volatile("cp.async.wait_group 0;\n" ::: "memory");
        else
            asm volatile("cp.async.wait_group 1;\n" ::: "memory");
        __syncthreads();

        if (kt + 2 < KTILES)
            load_stage((kt + 2) % NSTAGE, (kt + 2) * BK);

        const uint32_t sbase = smb + (kt % NSTAGE) * STG_BYTES;
        const uint32_t aB = sbase + aRowOff;
        const uint32_t bB = sbase + bRowOff;
        #pragma unroll
        for (int kk = 0; kk < BK; kk += 16) {
            uint32_t af[2][4];
            #pragma unroll
            for (int mi = 0; mi < 2; mi++)
                ldsm4(af[mi][0], af[mi][1], af[mi][2], af[mi][3],
                      aB + (mi * 16 * SSTRIDE + kk) * 2);
            uint32_t bfr[8][2];
            #pragma unroll
            for (int p = 0; p < 4; p++)
                ldsm4(bfr[2 * p][0], bfr[2 * p][1], bfr[2 * p + 1][0], bfr[2 * p + 1][1],
                      bB + (p * 16 * SSTRIDE + kk) * 2);
            #pragma unroll
            for (int mi = 0; mi < 2; mi++)
                #pragma unroll
                for (int ni = 0; ni < 8; ni++) {
                    asm volatile(
                        "mma.sync.aligned.m16n8k16.row.col.f32.bf16.bf16.f32 "
                        "{%0,%1,%2,%3}, {%4,%5,%6,%7}, {%8,%9}, {%0,%1,%2,%3};\n"
                        : "+f"(acc[mi][ni][0]), "+f"(acc[mi][ni][1]),
                          "+f"(acc[mi][ni][2]), "+f"(acc[mi][ni][3])
                        : "r"(af[mi][0]), "r"(af[mi][1]), "r"(af[mi][2]), "r"(af[mi][3]),
                          "r"(bfr[ni][0]), "r"(bfr[ni][1]));
                }
        }
        // no trailing sync: next iteration's wait+sync protects stage reuse
    }
    __syncthreads();

    // ---- epilogue: scores in place, per-row minima, candidate append ----
    float tm[2][2] = {{FLT_MAX, FLT_MAX}, {FLT_MAX, FLT_MAX}};
    #pragma unroll
    for (int ni = 0; ni < 8; ni++) {
        float2 cq = __ldg(reinterpret_cast<const float2*>(g_csq + colBase + wn * 64 + ni * 8 + t4 * 2));
        #pragma unroll
        for (int mi = 0; mi < 2; mi++) {
            acc[mi][ni][0] = fmaf(-2.0f, acc[mi][ni][0], cq.x);
            acc[mi][ni][1] = fmaf(-2.0f, acc[mi][ni][1], cq.y);
            acc[mi][ni][2] = fmaf(-2.0f, acc[mi][ni][2], cq.x);
            acc[mi][ni][3] = fmaf(-2.0f, acc[mi][ni][3], cq.y);
            tm[mi][0] = fminf(tm[mi][0], fminf(acc[mi][ni][0], acc[mi][ni][1]));
            tm[mi][1] = fminf(tm[mi][1], fminf(acc[mi][ni][2], acc[mi][ni][3]));
        }
    }
    #pragma unroll
    for (int mi = 0; mi < 2; mi++)
        #pragma unroll
        for (int h = 0; h < 2; h++)
            atomicMin(&s_min[wm * 32 + mi * 16 + g + h * 8], fenc(tm[mi][h]));
    __syncthreads();

    // merge block min into global running row-min; pull tighter bound back in
    if (t4 == 0) {
        #pragma unroll
        for (int mi = 0; mi < 2; mi++)
            #pragma unroll
            for (int h = 0; h < 2; h++) {
                int lr = wm * 32 + mi * 16 + g + h * 8;
                unsigned mine = s_min[lr];
                unsigned oldg = atomicMin(&g_rowmin[rowBase + lr], mine);
                if (oldg < mine) atomicMin(&s_min[lr], oldg);
            }
    }
    __syncthreads();

    // append candidates within MARGIN of best-known min (superset of final margin set)
    #pragma unroll
    for (int mi = 0; mi < 2; mi++) {
        #pragma unroll
        for (int h = 0; h < 2; h++) {
            const int lr = wm * 32 + mi * 16 + g + h * 8;
            const float th = fdec(s_min[lr]) + MARGIN;
            const int grow = rowBase + lr;
            #pragma unroll
            for (int ni = 0; ni < 8; ni++) {
                #pragma unroll
                for (int e = 0; e < 2; e++) {
                    float sv = acc[mi][ni][h * 2 + e];
                    if (sv <= th) {
                        int k = colBase + wn * 64 + ni * 8 + t4 * 2 + e;
                        int p = atomicAdd(&g_cnt[grow], 1);
                        if (p < GCAND)
                            g_cand[(size_t)grow * GCAND + p] = make_float2(sv, __int_as_float(k));
                    }
                }
            }
        }
    }
}

// ---------------- K3: lane-parallel filter + warp fp64 rescore + fused scatter ----------------
__global__ __launch_bounds__(256) void k_assign(const float* __restrict__ x,
                                                const float* __restrict__ cent) {
    const int tid = threadIdx.x;
    const int warp = tid >> 5, lane = tid & 31;
    const int row = blockIdx.x * 8 + warp;

    int cnt = g_cnt[row];
    if (cnt > GCAND) cnt = GCAND;
    const float th = fdec(g_rowmin[row]) + MARGIN;

    float2 cand = make_float2(FLT_MAX, 0.0f);
    if (lane < cnt) cand = g_cand[(size_t)row * GCAND + lane];
    unsigned mask = __ballot_sync(0xffffffffu, lane < cnt && cand.x <= th);

    const float* xr = x + (size_t)row * DIM + lane * 8;
    float4 xa = *reinterpret_cast<const float4*>(xr);
    float4 xb = *reinterpret_cast<const float4*>(xr + 4);

    int kstar;
    if (__popc(mask) == 1) {
        // single survivor: it is the argmin; no rescore needed
        int src = __ffs(mask) - 1;
        kstar = __shfl_sync(0xffffffffu, __float_as_int(cand.y), src);
    } else {
        double bestS = DBL_MAX;
        int bestK = INT_MAX;
        unsigned m = mask;
        while (m) {
            const int src = __ffs(m) - 1;
            m &= m - 1;
            const int k = __shfl_sync(0xffffffffu, __float_as_int(cand.y), src);
            const float* crow = cent + (size_t)k * DIM + lane * 8;
            float4 c0 = *reinterpret_cast<const float4*>(crow);
            float4 c1 = *reinterpret_cast<const float4*>(crow + 4);
            double dot = 0.0, cs = 0.0, cv;
            cv = (double)c0.x; dot += cv * (double)xa.x; cs += cv * cv;
            cv = (double)c0.y; dot += cv * (double)xa.y; cs += cv * cv;
            cv = (double)c0.z; dot += cv * (double)xa.z; cs += cv * cv;
            cv = (double)c0.w; dot += cv * (double)xa.w; cs += cv * cv;
            cv = (double)c1.x; dot += cv * (double)xb.x; cs += cv * cv;
            cv = (double)c1.y; dot += cv * (double)xb.y; cs += cv * cv;
            cv = (double)c1.z; dot += cv * (double)xb.z; cs += cv * cv;
            cv = (double)c1.w; dot += cv * (double)xb.w; cs += cv * cv;
            #pragma unroll
            for (int off = 16; off; off >>= 1) {
                dot += __shfl_xor_sync(0xffffffffu, dot, off);
                cs  += __shfl_xor_sync(0xffffffffu, cs,  off);
            }
            double sc = cs - 2.0 * dot;
            if (sc < bestS || (sc == bestS && k < bestK)) { bestS = sc; bestK = k; }
        }
        kstar = bestK;
    }

    if (lane == 0) atomicAdd(&g_counts[kstar], 1);
    float* dst = g_sums + (size_t)kstar * DIM + lane * 8;
    asm volatile("red.global.add.v4.f32 [%0], {%1,%2,%3,%4};\n"
                 :: "l"(dst), "f"(xa.x), "f"(xa.y), "f"(xa.z), "f"(xa.w) : "memory");
    asm volatile("red.global.add.v4.f32 [%0], {%1,%2,%3,%4};\n"
                 :: "l"(dst + 4), "f"(xb.x), "f"(xb.y), "f"(xb.z), "f"(xb.w) : "memory");
}

// ---------------- K4: finalize ----------------
__global__ void k_finalize(const float* __restrict__ cent, float* __restrict__ out) {
    int i = blockIdx.x * blockDim.x + threadIdx.x;
    if (i >= N_CENT * DIM) return;
    int k = i >> 8;
    int cnt = g_counts[k];
    out[i] = (cnt > 0) ? (g_sums[i] / (float)cnt) : cent[i];
}

// ---------------- launcher ----------------
extern "C" void kernel_launch(void* const* d_in, const int* in_sizes, int n_in,
                              void* d_out, int out_size) {
    const float* x    = (const float*)d_in[0];   // (131072, 256)
    const float* cent = (const float*)d_in[1];   // (2048, 256)
    float* out = (float*)d_out;                  // (2048, 256)

    cudaFuncSetAttribute(k_gemm, cudaFuncAttributeMaxDynamicSharedMemorySize, SM_TOTAL);

    k_prep<<<(N_SAMPLES * DIM / 4 + 255) / 256, 256>>>(x, cent);

    dim3 gg(N_SAMPLES / BM, N_CENT / BN);
    k_gemm<<<gg, 256, SM_TOTAL>>>();

    k_assign<<<N_SAMPLES / 8, 256>>>(x, cent);

    k_finalize<<<(N_CENT * DIM + 255) / 256, 256>>>(cent, out);
}

// round 16
// speedup vs baseline: 2.4743x; 1.0293x over previous
#include <cuda_runtime.h>
#include <cuda_bf16.h>
#include <cuda_fp16.h>
#include <cstdint>
#include <cfloat>
#include <climits>

// Problem dims (fixed per reference)
#define N_SAMPLES 131072
#define N_CENT    2048
#define DIM       256

#define BM 128
#define BN 128
#define BK 64                 // halves per k-tile (doubled: fewer syncs)
#define SSTRIDE 72            // halves; 144B rows -> 16B aligned + LDSM conflict-free
#define KTILES (DIM / BK)     // 4
#define NSTAGE 3

#define MARGIN 3.0f
#define GCAND  32

// ---------------- scratch (static device globals; no runtime alloc) ----------------
__device__ __nv_bfloat16 g_xb[(size_t)N_SAMPLES * DIM];   // x in bf16 (64 MB)
__device__ __nv_bfloat16 g_cb[(size_t)N_CENT * DIM];      // centroids bf16 (1 MB)
__device__ float         g_csq[N_CENT];                    // ||c||^2 fp32
__device__ float         g_sums[(size_t)N_CENT * DIM];     // scatter sums
__device__ int           g_counts[N_CENT];
__device__ unsigned      g_rowmin[N_SAMPLES];              // order-encoded running min per row
__device__ int           g_cnt[N_SAMPLES];                 // candidates per row
__device__ float2        g_cand[(size_t)N_SAMPLES * GCAND];// (score, k-as-float-bits)

// ---------------- helpers ----------------
__device__ __forceinline__ void cp_async16(uint32_t smem_addr, const void* gptr) {
    asm volatile("cp.async.cg.shared.global [%0], [%1], 16;\n"
                 :: "r"(smem_addr), "l"(gptr));
}
__device__ __forceinline__ void ldsm4(uint32_t& r0, uint32_t& r1, uint32_t& r2, uint32_t& r3,
                                      uint32_t addr) {
    asm volatile("ldmatrix.sync.aligned.m8n8.x4.shared.b16 {%0,%1,%2,%3}, [%4];"
                 : "=r"(r0), "=r"(r1), "=r"(r2), "=r"(r3) : "r"(addr));
}
__device__ __forceinline__ unsigned fenc(float f) {
    unsigned u = __float_as_uint(f);
    return (u & 0x80000000u) ? ~u : (u | 0x80000000u);
}
__device__ __forceinline__ float fdec(unsigned u) {
    u = (u & 0x80000000u) ? (u & 0x7FFFFFFFu) : ~u;
    return __uint_as_float(u);
}

// ---------------- K1: fused prep: zero scratch + convert x & centroids ----------------
__global__ void k_prep(const float* __restrict__ x, const float* __restrict__ c) {
    const size_t i = (size_t)blockIdx.x * blockDim.x + threadIdx.x;

    const size_t n4 = (size_t)N_SAMPLES * DIM / 4;
    if (i < n4) {
        float4 v = reinterpret_cast<const float4*>(x)[i];
        __nv_bfloat162 p0 = __nv_bfloat162(__float2bfloat16(v.x), __float2bfloat16(v.y));
        __nv_bfloat162 p1 = __nv_bfloat162(__float2bfloat16(v.z), __float2bfloat16(v.w));
        *reinterpret_cast<__nv_bfloat162*>(g_xb + i * 4)     = p0;
        *reinterpret_cast<__nv_bfloat162*>(g_xb + i * 4 + 2) = p1;
    }
    if (i < (size_t)N_CENT * DIM) g_sums[i] = 0.0f;
    if (i < N_SAMPLES) { g_cnt[i] = 0; g_rowmin[i] = 0xFFFFFFFFu; }
    if (i < N_CENT) g_counts[i] = 0;

    const int w = (int)(i >> 5);
    const int lane = threadIdx.x & 31;
    if (w < N_CENT) {
        const float* row = c + (size_t)w * DIM + lane * 8;
        float4 a = *reinterpret_cast<const float4*>(row);
        float4 b = *reinterpret_cast<const float4*>(row + 4);
        __nv_bfloat16* dst = g_cb + (size_t)w * DIM + lane * 8;
        dst[0] = __float2bfloat16(a.x); dst[1] = __float2bfloat16(a.y);
        dst[2] = __float2bfloat16(a.z); dst[3] = __float2bfloat16(a.w);
        dst[4] = __float2bfloat16(b.x); dst[5] = __float2bfloat16(b.y);
        dst[6] = __float2bfloat16(b.z); dst[7] = __float2bfloat16(b.w);
        float s = a.x*a.x + a.y*a.y + a.z*a.z + a.w*a.w
                + b.x*b.x + b.y*b.y + b.z*b.z + b.w*b.w;
        #pragma unroll
        for (int off = 16; off; off >>= 1) s += __shfl_xor_sync(0xffffffffu, s, off);
        if (lane == 0) g_csq[w] = s;
    }
}

// smem: 3 stages of (A tile + B tile) + row-min
// per-stage: A 128*72*2 = 18432 B, B same -> 36864 B/stage; 3 stages = 110592
#define A_BYTES   18432
#define STG_BYTES 36864
#define SM_MIN    (NSTAGE * STG_BYTES)
#define SM_TOTAL  (SM_MIN + 512)

extern __shared__ unsigned char s_raw[];

// ---------------- K2: MMA GEMM, 3-stage BK=64 pipeline, min/candidate epilogue ----------------
__global__ __launch_bounds__(256, 2) void k_gemm() {
    const int tid  = threadIdx.x;
    const int warp = tid >> 5, lane = tid & 31;
    const int wm = warp & 3, wn = warp >> 2;
    const int g  = lane >> 2, t4 = lane & 3;
    const int rowBase = blockIdx.x * BM;
    const int colBase = blockIdx.y * BN;

    unsigned* s_min = reinterpret_cast<unsigned*>(s_raw + SM_MIN);
    if (tid < BM) s_min[tid] = 0xFFFFFFFFu;

    const uint32_t smb = (uint32_t)__cvta_generic_to_shared(s_raw);

    // cooperative-load coords: 1024 16B-chunks per matrix per stage, 4 per thread
    const int lr0 = tid >> 3;            // row 0..31 (+32*it)
    const int lch = (tid & 7) * 8;       // half offset within BK=64

    // ldmatrix per-lane offsets (bytes, within a stage)
    const int lrow = lane & 7, sel = lane >> 3;
    const uint32_t aRowOff = ((wm * 32 + (sel & 1) * 8 + lrow) * SSTRIDE + (sel >> 1) * 8) * 2;
    const uint32_t bRowOff = A_BYTES + ((wn * 64 + (sel >> 1) * 8 + lrow) * SSTRIDE + (sel & 1) * 8) * 2;

    float acc[2][8][4];
    #pragma unroll
    for (int a = 0; a < 2; a++)
        #pragma unroll
        for (int b = 0; b < 8; b++)
            #pragma unroll
            for (int c = 0; c < 4; c++) acc[a][b][c] = 0.0f;

    auto load_stage = [&](int st, int k0) {
        uint32_t base = smb + st * STG_BYTES;
        #pragma unroll
        for (int it = 0; it < 4; it++) {
            int row = lr0 + it * 32;
            cp_async16(base + (row * SSTRIDE + lch) * 2,
                       g_xb + (size_t)(rowBase + row) * DIM + k0 + lch);
            cp_async16(base + A_BYTES + (row * SSTRIDE + lch) * 2,
                       g_cb + (size_t)(colBase + row) * DIM + k0 + lch);
        }
        asm volatile("cp.async.commit_group;\n" ::: "memory");
    };

    load_stage(0, 0);
    load_stage(1, BK);

    for (int kt = 0; kt < KTILES; kt++) {
        if (kt == KTILES - 1)
            asm volatile("cp.async.wait_group 0;\n" ::: "memory");
        else
            asm volatile("cp.async.wait_group 1;\n" ::: "memory");
        __syncthreads();

        if (kt + 2 < KTILES)
            load_stage((kt + 2) % NSTAGE, (kt + 2) * BK);

        const uint32_t sbase = smb + (kt % NSTAGE) * STG_BYTES;
        const uint32_t aB = sbase + aRowOff;
        const uint32_t bB = sbase + bRowOff;
        #pragma unroll
        for (int kk = 0; kk < BK; kk += 16) {
            uint32_t af[2][4];
            #pragma unroll
            for (int mi = 0; mi < 2; mi++)
                ldsm4(af[mi][0], af[mi][1], af[mi][2], af[mi][3],
                      aB + (mi * 16 * SSTRIDE + kk) * 2);
            uint32_t bfr[8][2];
            #pragma unroll
            for (int p = 0; p < 4; p++)
                ldsm4(bfr[2 * p][0], bfr[2 * p][1], bfr[2 * p + 1][0], bfr[2 * p + 1][1],
                      bB + (p * 16 * SSTRIDE + kk) * 2);
            #pragma unroll
            for (int mi = 0; mi < 2; mi++)
                #pragma unroll
                for (int ni = 0; ni < 8; ni++) {
                    asm volatile(
                        "mma.sync.aligned.m16n8k16.row.col.f32.bf16.bf16.f32 "
                        "{%0,%1,%2,%3}, {%4,%5,%6,%7}, {%8,%9}, {%0,%1,%2,%3};\n"
                        : "+f"(acc[mi][ni][0]), "+f"(acc[mi][ni][1]),
                          "+f"(acc[mi][ni][2]), "+f"(acc[mi][ni][3])
                        : "r"(af[mi][0]), "r"(af[mi][1]), "r"(af[mi][2]), "r"(af[mi][3]),
                          "r"(bfr[ni][0]), "r"(bfr[ni][1]));
                }
        }
        // no trailing sync: next iteration's wait+sync protects stage reuse
    }
    __syncthreads();

    // ---- epilogue: scores in place, per-row minima, candidate append ----
    float tm[2][2] = {{FLT_MAX, FLT_MAX}, {FLT_MAX, FLT_MAX}};
    #pragma unroll
    for (int ni = 0; ni < 8; ni++) {
        float2 cq = __ldg(reinterpret_cast<const float2*>(g_csq + colBase + wn * 64 + ni * 8 + t4 * 2));
        #pragma unroll
        for (int mi = 0; mi < 2; mi++) {
            acc[mi][ni][0] = fmaf(-2.0f, acc[mi][ni][0], cq.x);
            acc[mi][ni][1] = fmaf(-2.0f, acc[mi][ni][1], cq.y);
            acc[mi][ni][2] = fmaf(-2.0f, acc[mi][ni][2], cq.x);
            acc[mi][ni][3] = fmaf(-2.0f, acc[mi][ni][3], cq.y);
            tm[mi][0] = fminf(tm[mi][0], fminf(acc[mi][ni][0], acc[mi][ni][1]));
            tm[mi][1] = fminf(tm[mi][1], fminf(acc[mi][ni][2], acc[mi][ni][3]));
        }
    }
    #pragma unroll
    for (int mi = 0; mi < 2; mi++)
        #pragma unroll
        for (int h = 0; h < 2; h++)
            atomicMin(&s_min[wm * 32 + mi * 16 + g + h * 8], fenc(tm[mi][h]));
    __syncthreads();

    // merge block min into global running row-min; pull tighter bound back in
    if (t4 == 0) {
        #pragma unroll
        for (int mi = 0; mi < 2; mi++)
            #pragma unroll
            for (int h = 0; h < 2; h++) {
                int lr = wm * 32 + mi * 16 + g + h * 8;
                unsigned mine = s_min[lr];
                unsigned oldg = atomicMin(&g_rowmin[rowBase + lr], mine);
                if (oldg < mine) atomicMin(&s_min[lr], oldg);
            }
    }
    __syncthreads();

    // append candidates within MARGIN of best-known min (superset of final margin set)
    #pragma unroll
    for (int mi = 0; mi < 2; mi++) {
        #pragma unroll
        for (int h = 0; h < 2; h++) {
            const int lr = wm * 32 + mi * 16 + g + h * 8;
            const float th = fdec(s_min[lr]) + MARGIN;
            const int grow = rowBase + lr;
            #pragma unroll
            for (int ni = 0; ni < 8; ni++) {
                #pragma unroll
                for (int e = 0; e < 2; e++) {
                    float sv = acc[mi][ni][h * 2 + e];
                    if (sv <= th) {
                        int k = colBase + wn * 64 + ni * 8 + t4 * 2 + e;
                        int p = atomicAdd(&g_cnt[grow], 1);
                        if (p < GCAND)
                            g_cand[(size_t)grow * GCAND + p] = make_float2(sv, __int_as_float(k));
                    }
                }
            }
        }
    }
}

// ---------------- K3: lane-parallel filter + warp fp64 rescore + fused scatter ----------------
__global__ __launch_bounds__(256) void k_assign(const float* __restrict__ x,
                                                const float* __restrict__ cent) {
    const int tid = threadIdx.x;
    const int warp = tid >> 5, lane = tid & 31;
    const int row = blockIdx.x * 8 + warp;

    int cnt = g_cnt[row];
    if (cnt > GCAND) cnt = GCAND;
    const float th = fdec(g_rowmin[row]) + MARGIN;

    float2 cand = make_float2(FLT_MAX, 0.0f);
    if (lane < cnt) cand = g_cand[(size_t)row * GCAND + lane];
    unsigned mask = __ballot_sync(0xffffffffu, lane < cnt && cand.x <= th);

    const float* xr = x + (size_t)row * DIM + lane * 8;
    float4 xa = *reinterpret_cast<const float4*>(xr);
    float4 xb = *reinterpret_cast<const float4*>(xr + 4);

    int kstar;
    if (__popc(mask) == 1) {
        // single survivor: it is the argmin; no rescore needed
        int src = __ffs(mask) - 1;
        kstar = __shfl_sync(0xffffffffu, __float_as_int(cand.y), src);
    } else {
        double bestS = DBL_MAX;
        int bestK = INT_MAX;
        unsigned m = mask;
        while (m) {
            const int src = __ffs(m) - 1;
            m &= m - 1;
            const int k = __shfl_sync(0xffffffffu, __float_as_int(cand.y), src);
            const float* crow = cent + (size_t)k * DIM + lane * 8;
            float4 c0 = *reinterpret_cast<const float4*>(crow);
            float4 c1 = *reinterpret_cast<const float4*>(crow + 4);
            double dot = 0.0, cs = 0.0, cv;
            cv = (double)c0.x; dot += cv * (double)xa.x; cs += cv * cv;
            cv = (double)c0.y; dot += cv * (double)xa.y; cs += cv * cv;
            cv = (double)c0.z; dot += cv * (double)xa.z; cs += cv * cv;
            cv = (double)c0.w; dot += cv * (double)xa.w; cs += cv * cv;
            cv = (double)c1.x; dot += cv * (double)xb.x; cs += cv * cv;
            cv = (double)c1.y; dot += cv * (double)xb.y; cs += cv * cv;
            cv = (double)c1.z; dot += cv * (double)xb.z; cs += cv * cv;
            cv = (double)c1.w; dot += cv * (double)xb.w; cs += cv * cv;
            #pragma unroll
            for (int off = 16; off; off >>= 1) {
                dot += __shfl_xor_sync(0xffffffffu, dot, off);
                cs  += __shfl_xor_sync(0xffffffffu, cs,  off);
            }
            double sc = cs - 2.0 * dot;
            if (sc < bestS || (sc == bestS && k < bestK)) { bestS = sc; bestK = k; }
        }
        kstar = bestK;
    }

    if (lane == 0) atomicAdd(&g_counts[kstar], 1);
    float* dst = g_sums + (size_t)kstar * DIM + lane * 8;
    asm volatile("red.global.add.v4.f32 [%0], {%1,%2,%3,%4};\n"
                 :: "l"(dst), "f"(xa.x), "f"(xa.y), "f"(xa.z), "f"(xa.w) : "memory");
    asm volatile("red.global.add.v4.f32 [%0], {%1,%2,%3,%4};\n"
                 :: "l"(dst + 4), "f"(xb.x), "f"(xb.y), "f"(xb.z), "f"(xb.w) : "memory");
}

// ---------------- K4: finalize ----------------
__global__ void k_finalize(const float* __restrict__ cent, float* __restrict__ out) {
    int i = blockIdx.x * blockDim.x + threadIdx.x;
    if (i >= N_CENT * DIM) return;
    int k = i >> 8;
    int cnt = g_counts[k];
    out[i] = (cnt > 0) ? (g_sums[i] / (float)cnt) : cent[i];
}

// ---------------- launcher ----------------
extern "C" void kernel_launch(void* const* d_in, const int* in_sizes, int n_in,
                              void* d_out, int out_size) {
    const float* x    = (const float*)d_in[0];   // (131072, 256)
    const float* cent = (const float*)d_in[1];   // (2048, 256)
    float* out = (float*)d_out;                  // (2048, 256)

    cudaFuncSetAttribute(k_gemm, cudaFuncAttributeMaxDynamicSharedMemorySize, SM_TOTAL);

    k_prep<<<(N_SAMPLES * DIM / 4 + 255) / 256, 256>>>(x, cent);

    dim3 gg(N_SAMPLES / BM, N_CENT / BN);
    k_gemm<<<gg, 256, SM_TOTAL>>>();

    k_assign<<<N_SAMPLES / 8, 256>>>(x, cent);

    k_finalize<<<(N_CENT * DIM + 255) / 256, 256>>>(cent, out);
}